// round 4
// baseline (speedup 1.0000x reference)
#include <cuda_runtime.h>
#include <math.h>

// ---------------------------------------------------------------------------
// FullyConnectedSteerableGeometricProductLayer  (Cl(3,0) geometric algebra)
//
// Restructured as:
//   1) transpose x (B,N,8) -> xT[8][B*N]                    (coalesced GEMM A)
//   2) xr GEMMs: xrT[i] = xT[i] @ wrT[grade(i)]^T           (8 GEMMs, K=512)
//   3) per-(b,n): grade-norm gating of xr + build 52 feature columns
//        F[b][c][n]  (44 Cayley (path,outblade) combos + 8 left passthrough)
//   4) Wbig[m][c][n] gathered from weight (paths) / w_left (grades)
//   5) 8 GEMMs: out[:, :, j] = F_j @ Wbig_j^T, K_j = 512*{5 or 7},
//      epilogue adds b_left (j==0 only) and scales by 1/sqrt(2)
// ---------------------------------------------------------------------------

#define BB   2048
#define NIN  512
#define NOUT 512
#define BN   (BB*NIN)        // 1048576
#define MN   (NOUT*NIN)      // 262144
#define NC   52

// scratch (static device arrays; no allocation in kernel_launch)
__device__ __align__(256) float g_xT [8u  * BN];          //  33.5 MB
__device__ __align__(256) float g_xrT[8u  * BN];          //  33.5 MB
__device__ __align__(256) float g_wrT[4u  * MN];          //   4.2 MB
__device__ __align__(256) float g_Wb [(size_t)NOUT*NC*NIN]; // 54.5 MB
__device__ __align__(256) float g_F  [(size_t)BB  *NC*NIN]; // 218 MB

// blade grades:  1, e1,e2,e3, e12,e13,e23, e123
__constant__ int c_grade[8] = {0,1,1,1,2,2,2,3};
// per output-blade j: start column / column count in the 52-wide feature space
__constant__ int c_start[8] = {0,5,12,19,26,33,40,47};
__constant__ int c_cnt  [8] = {5,7,7,7,7,7,7,5};
// per feature column: weight source.  <4 : w_left grade g ;  >=4 : weight path (s-4)
__constant__ int c_wsrc[NC] = {
    0, 4, 8,14,20,                 // j=0 : L g0, P0, P4, P10, P16
    1, 5, 9,10,15,16,21,           // j=1 : L g1, P1, P5, P6, P11, P12, P17
    1, 5, 9,10,15,16,21,           // j=2
    1, 5, 9,10,15,16,21,           // j=3
    2, 6,11,12,17,18,22,           // j=4 : L g2, P2, P7, P8, P13, P14, P18
    2, 6,11,12,17,18,22,           // j=5
    2, 6,11,12,17,18,22,           // j=6
    3, 7,13,19,23                  // j=7 : L g3, P3, P9, P15, P19
};

// ---------------------------------------------------------------------------
// transpose x (b,n,8) -> xT[i][b*N+n]
__global__ void __launch_bounds__(256) k_transpose_x(const float* __restrict__ x)
{
    int idx = blockIdx.x * 256 + threadIdx.x;   // (b,n)
    float4 v0 = ((const float4*)x)[2*idx];
    float4 v1 = ((const float4*)x)[2*idx + 1];
    g_xT[0u*BN + idx] = v0.x;  g_xT[1u*BN + idx] = v0.y;
    g_xT[2u*BN + idx] = v0.z;  g_xT[3u*BN + idx] = v0.w;
    g_xT[4u*BN + idx] = v1.x;  g_xT[5u*BN + idx] = v1.y;
    g_xT[6u*BN + idx] = v1.z;  g_xT[7u*BN + idx] = v1.w;
}

// wrT[g][m*N+n] = w_right[m][n][g];   Wbig[m][c][n] from weight / w_left
__global__ void __launch_bounds__(256) k_prep_w(const float* __restrict__ w_right,
                                                const float* __restrict__ weight,
                                                const float* __restrict__ w_left)
{
    int idx = blockIdx.x * 256 + threadIdx.x;   // m*NIN + n
    float4 wr4 = ((const float4*)w_right)[idx];
    g_wrT[0u*MN + idx] = wr4.x;  g_wrT[1u*MN + idx] = wr4.y;
    g_wrT[2u*MN + idx] = wr4.z;  g_wrT[3u*MN + idx] = wr4.w;

    int m = idx >> 9;
    int n = idx & (NIN - 1);
    const float* wp  = weight + (size_t)idx * 20;
    const float* wlp = w_left + (size_t)idx * 4;
    size_t base = (size_t)m * NC * NIN + n;
    #pragma unroll
    for (int c = 0; c < NC; ++c) {
        int s = c_wsrc[c];
        float v = (s < 4) ? wlp[s] : wp[s - 4];
        g_Wb[base + (size_t)c * NIN] = v;
    }
}

// ---------------------------------------------------------------------------
// SGEMM body: C[r][c] = alpha * ( sum_k A[r*lda+k]*B[c*ldb+k] + bias[c]? )
// 128x128 tile, KT=8, 256 threads, 8x8 microtile.  M multiple of 128 (grid.y),
// N multiple of 128 (grid.x), K multiple of 8.
__device__ __forceinline__ void sgemm_body(
    const float* __restrict__ A, int lda,
    const float* __restrict__ Bm, int ldb,
    float* __restrict__ C, int ldcr, int ldcc,
    int K, float alpha, const float* __restrict__ bias)
{
    __shared__ float As[8][128];
    __shared__ float Bs[8][128];

    int tid  = threadIdx.x;
    int tx   = tid & 15;        // col microtile 0..15
    int ty   = tid >> 4;        // row microtile 0..15
    int row0 = blockIdx.y * 128;
    int col0 = blockIdx.x * 128;
    int lrow = tid >> 1;        // 0..127
    int lk   = (tid & 1) * 4;   // 0 or 4

    const float* Ag = A  + (size_t)(row0 + lrow) * lda + lk;
    const float* Bg = Bm + (size_t)(col0 + lrow) * ldb + lk;

    float acc[8][8];
    #pragma unroll
    for (int i = 0; i < 8; ++i)
        #pragma unroll
        for (int j = 0; j < 8; ++j) acc[i][j] = 0.f;

    float4 av = *(const float4*)Ag;
    float4 bv = *(const float4*)Bg;

    for (int k0 = 0; k0 < K; k0 += 8) {
        __syncthreads();
        As[lk+0][lrow] = av.x; As[lk+1][lrow] = av.y;
        As[lk+2][lrow] = av.z; As[lk+3][lrow] = av.w;
        Bs[lk+0][lrow] = bv.x; Bs[lk+1][lrow] = bv.y;
        Bs[lk+2][lrow] = bv.z; Bs[lk+3][lrow] = bv.w;
        __syncthreads();

        float4 avn = av, bvn = bv;
        if (k0 + 8 < K) {
            avn = *(const float4*)(Ag + k0 + 8);
            bvn = *(const float4*)(Bg + k0 + 8);
        }

        #pragma unroll
        for (int kk = 0; kk < 8; ++kk) {
            float4 a0 = *(const float4*)&As[kk][ty*8];
            float4 a1 = *(const float4*)&As[kk][ty*8 + 4];
            float4 b0 = *(const float4*)&Bs[kk][tx*8];
            float4 b1 = *(const float4*)&Bs[kk][tx*8 + 4];
            float ar[8] = {a0.x,a0.y,a0.z,a0.w,a1.x,a1.y,a1.z,a1.w};
            float br[8] = {b0.x,b0.y,b0.z,b0.w,b1.x,b1.y,b1.z,b1.w};
            #pragma unroll
            for (int i = 0; i < 8; ++i)
                #pragma unroll
                for (int j = 0; j < 8; ++j)
                    acc[i][j] = fmaf(ar[i], br[j], acc[i][j]);
        }
        av = avn; bv = bvn;
    }

    #pragma unroll
    for (int i = 0; i < 8; ++i) {
        int r = row0 + ty*8 + i;
        #pragma unroll
        for (int j = 0; j < 8; ++j) {
            int cix = col0 + tx*8 + j;
            float v = acc[i][j];
            if (bias) v += bias[cix];
            C[(size_t)r * ldcr + (size_t)cix * ldcc] = v * alpha;
        }
    }
}

// xr GEMMs: grid (NOUT/128, B/128, 8)
__global__ void __launch_bounds__(256) k_gemm_xr()
{
    int i = blockIdx.z;
    int g = c_grade[i];
    sgemm_body(g_xT  + (size_t)i * BN, NIN,
               g_wrT + (size_t)g * MN, NIN,
               g_xrT + (size_t)i * BN, NIN, 1,
               NIN, 1.0f, nullptr);
}

__device__ __forceinline__ float sigf(float a) { return 1.0f / (1.0f + expf(-a)); }

// normalization + 52 feature columns
__global__ void __launch_bounds__(256) k_features(const float* __restrict__ x,
                                                  const float* __restrict__ norm_a)
{
    int idx = blockIdx.x * 256 + threadIdx.x;   // b*NIN + n
    int n = idx & (NIN - 1);
    int b = idx >> 9;

    float4 v0 = ((const float4*)x)[2*idx];
    float4 v1 = ((const float4*)x)[2*idx + 1];
    float x0=v0.x, x1=v0.y, x2=v0.z, x3=v0.w, x4=v1.x, x5=v1.y, x6=v1.z, x7=v1.w;

    float r0=g_xrT[0u*BN+idx], r1=g_xrT[1u*BN+idx], r2=g_xrT[2u*BN+idx],
          r3=g_xrT[3u*BN+idx], r4=g_xrT[4u*BN+idx], r5=g_xrT[5u*BN+idx],
          r6=g_xrT[6u*BN+idx], r7=g_xrT[7u*BN+idx];

    float4 na = ((const float4*)norm_a)[n];
    float s0 = r0*r0;
    float s1 = r1*r1 + r2*r2 + r3*r3;
    float s2 = r4*r4 + r5*r5 + r6*r6;
    float s3 = r7*r7;
    float i0 = 1.0f / (sigf(na.x) * (sqrtf(s0) - 1.0f) + 1.0f + 1e-6f);
    float i1 = 1.0f / (sigf(na.y) * (sqrtf(s1) - 1.0f) + 1.0f + 1e-6f);
    float i2 = 1.0f / (sigf(na.z) * (sqrtf(s2) - 1.0f) + 1.0f + 1e-6f);
    float i3 = 1.0f / (sigf(na.w) * (sqrtf(s3) - 1.0f) + 1.0f + 1e-6f);
    r0*=i0; r1*=i1; r2*=i1; r3*=i1; r4*=i2; r5*=i2; r6*=i2; r7*=i3;

    float f[NC];
    // j=0 (scalar)
    f[0]=x0;  f[1]=x0*r0;
    f[2]=x1*r1 + x2*r2 + x3*r3;
    f[3]=-(x4*r4 + x5*r5 + x6*r6);
    f[4]=-x7*r7;
    // j=1 (e1)
    f[5]=x1;  f[6]=x0*r1;  f[7]=x1*r0;
    f[8]=-x2*r4 - x3*r5;   f[9]= x4*r2 + x5*r3;
    f[10]=-x6*r7;          f[11]=-x7*r6;
    // j=2 (e2)
    f[12]=x2; f[13]=x0*r2; f[14]=x2*r0;
    f[15]= x1*r4 - x3*r6;  f[16]=-x4*r1 + x6*r3;
    f[17]= x5*r7;          f[18]= x7*r5;
    // j=3 (e3)
    f[19]=x3; f[20]=x0*r3; f[21]=x3*r0;
    f[22]= x1*r5 + x2*r6;  f[23]=-x5*r1 - x6*r2;
    f[24]=-x4*r7;          f[25]=-x7*r4;
    // j=4 (e12)
    f[26]=x4; f[27]=x0*r4; f[28]= x1*r2 - x2*r1;
    f[29]= x3*r7;          f[30]= x4*r0;
    f[31]=-x5*r6 + x6*r5;  f[32]= x7*r3;
    // j=5 (e13)
    f[33]=x5; f[34]=x0*r5; f[35]= x1*r3 - x3*r1;
    f[36]=-x2*r7;          f[37]= x5*r0;
    f[38]= x4*r6 - x6*r4;  f[39]=-x7*r2;
    // j=6 (e23)
    f[40]=x6; f[41]=x0*r6; f[42]= x2*r3 - x3*r2;
    f[43]= x1*r7;          f[44]= x6*r0;
    f[45]=-x4*r5 + x5*r4;  f[46]= x7*r1;
    // j=7 (e123)
    f[47]=x7; f[48]=x0*r7;
    f[49]= x1*r6 - x2*r5 + x3*r4;
    f[50]= x4*r3 - x5*r2 + x6*r1;
    f[51]= x7*r0;

    size_t base = (size_t)b * NC * NIN + n;
    #pragma unroll
    for (int c = 0; c < NC; ++c)
        g_F[base + (size_t)c * NIN] = f[c];
}

// output GEMMs: grid (NOUT/128, B/128, 8), epilogue bias (j==0) + 1/sqrt(2)
__global__ void __launch_bounds__(256) k_gemm_out(float* __restrict__ out,
                                                  const float* __restrict__ b_left)
{
    int j  = blockIdx.z;
    int st = c_start[j];
    int K  = c_cnt[j] * NIN;
    sgemm_body(g_F  + (size_t)st * NIN, NC * NIN,
               g_Wb + (size_t)st * NIN, NC * NIN,
               out + j, NOUT * 8, 8,
               K, 0.7071067811865475f, (j == 0) ? b_left : nullptr);
}

// ---------------------------------------------------------------------------
extern "C" void kernel_launch(void* const* d_in, const int* in_sizes, int n_in,
                              void* d_out, int out_size)
{
    const float* x       = (const float*)d_in[0];   // (2048, 512, 8)
    const float* weight  = (const float*)d_in[1];   // (512, 512, 20)
    const float* w_right = (const float*)d_in[2];   // (512, 512, 4)
    const float* w_left  = (const float*)d_in[3];   // (512, 512, 4)
    const float* b_left  = (const float*)d_in[4];   // (512,)
    const float* norm_a  = (const float*)d_in[5];   // (1, 512, 4)
    float* out = (float*)d_out;                     // (2048, 512, 8)

    k_transpose_x<<<BN / 256, 256>>>(x);
    k_prep_w<<<MN / 256, 256>>>(w_right, weight, w_left);

    dim3 gemm_grid(NOUT / 128, BB / 128, 8);
    k_gemm_xr<<<gemm_grid, 256>>>();
    k_features<<<BN / 256, 256>>>(x, norm_a);
    k_gemm_out<<<gemm_grid, 256>>>(out, b_left);
}

// round 10
// speedup vs baseline: 2.2046x; 2.2046x over previous
#include <cuda_runtime.h>
#include <cuda_bf16.h>
#include <math.h>
#include <stdint.h>

// ---------------------------------------------------------------------------
// FullyConnectedSteerableGeometricProductLayer — mma.sync split-bf16 version
// (tcgen05 unavailable: harness ptxas targets sm_103 without the 'a' suffix,
//  so we use the sm_80-era warp-level tensor path: ldmatrix + mma.m16n8k16)
//
//  C_fp32 ≈ Ah·Bh + Al·Bh + Ah·Bl  (bf16 hi/lo split, fp32 accumulators)
//
//  1) split x        -> xh/xl        [8][2048][512] bf16
//  2) split weights  -> wrh/wrl, Wbh/Wbl (52-col gathered big weight)
//  3) GEMM1: xr[i] = x_i · wr_{g(i)}^T     (K=512, 3 phases)
//  4) features: norm gating + 52 feature cols -> Fh/Fl bf16
//  5) GEMM2: outT[j] = F_j · Wb_j^T        (K=2560/3584, 3 phases)
//     epilogue: (+b_left for j=0) * 1/sqrt(2)
//  6) finalize transpose outT[j][b][m] -> out[b][m][j]
// ---------------------------------------------------------------------------

#define BB   2048
#define NIN  512
#define NOUT 512
#define BN   (BB*NIN)            // 1048576
#define MN   (NOUT*NIN)          // 262144
#define NC   52
#define WCOLS (NC*NIN)           // 26624

// GEMM tiling
#define KT        64
#define SSTAGES   4
#define ROWSTRIDE 144                       // 128B data + 16B pad (9 chunks, odd)
#define MAT_BYTES (128*ROWSTRIDE)           // 18432
#define STAGE_BYTES (2*MAT_BYTES)           // 36864
#define SMEM_BYTES (SSTAGES*STAGE_BYTES)    // 147456

// scratch (static device arrays; no allocation anywhere)
__device__ __align__(256) __nv_bfloat16 g_xh [8u*BN];
__device__ __align__(256) __nv_bfloat16 g_xl [8u*BN];
__device__ __align__(256) __nv_bfloat16 g_wrh[4u*MN];
__device__ __align__(256) __nv_bfloat16 g_wrl[4u*MN];
__device__ __align__(256) __nv_bfloat16 g_Wbh[(size_t)NOUT*WCOLS];
__device__ __align__(256) __nv_bfloat16 g_Wbl[(size_t)NOUT*WCOLS];
__device__ __align__(256) __nv_bfloat16 g_Fh [(size_t)BB*WCOLS];
__device__ __align__(256) __nv_bfloat16 g_Fl [(size_t)BB*WCOLS];
__device__ __align__(256) float         g_xr  [8u*BN];
__device__ __align__(256) float         g_outT[8u*BN];

__constant__ int cc_grade[8] = {0,1,1,1,2,2,2,3};
__constant__ int cc_start[8] = {0,5,12,19,26,33,40,47};
__constant__ int cc_cnt [8]  = {5,7,7,7,7,7,7,5};
__constant__ int cc_wsrc[NC] = {
    0, 4, 8,14,20,
    1, 5, 9,10,15,16,21,
    1, 5, 9,10,15,16,21,
    1, 5, 9,10,15,16,21,
    2, 6,11,12,17,18,22,
    2, 6,11,12,17,18,22,
    2, 6,11,12,17,18,22,
    3, 7,13,19,23
};

// ---------------------------------------------------------------------------
// helpers
// ---------------------------------------------------------------------------
__device__ __forceinline__ uint32_t smem_u32(const void* p) {
    uint32_t a;
    asm("{ .reg .u64 t; cvta.to.shared.u64 t, %1; cvt.u32.u64 %0, t; }"
        : "=r"(a) : "l"(p));
    return a;
}
__device__ __forceinline__ void cp16(uint32_t dst, const void* src) {
    asm volatile("cp.async.cg.shared.global [%0], [%1], 16;"
                 :: "r"(dst), "l"(__cvta_generic_to_global(src)));
}
__device__ __forceinline__ void ldsm4(uint32_t* r, uint32_t addr) {
    asm volatile("ldmatrix.sync.aligned.m8n8.x4.shared.b16 {%0,%1,%2,%3}, [%4];"
        : "=r"(r[0]), "=r"(r[1]), "=r"(r[2]), "=r"(r[3]) : "r"(addr));
}
__device__ __forceinline__ void mma16816(float* c, const uint32_t* a,
                                         uint32_t b0, uint32_t b1) {
    asm volatile("mma.sync.aligned.m16n8k16.row.col.f32.bf16.bf16.f32 "
        "{%0,%1,%2,%3}, {%4,%5,%6,%7}, {%8,%9}, {%0,%1,%2,%3};"
        : "+f"(c[0]), "+f"(c[1]), "+f"(c[2]), "+f"(c[3])
        : "r"(a[0]), "r"(a[1]), "r"(a[2]), "r"(a[3]), "r"(b0), "r"(b1));
}
__device__ __forceinline__ void split2(float v, __nv_bfloat16& h, __nv_bfloat16& l) {
    h = __float2bfloat16(v);
    l = __float2bfloat16(v - __bfloat162float(h));
}

// ---------------------------------------------------------------------------
// prep kernels
// ---------------------------------------------------------------------------
__global__ void __launch_bounds__(256) k_split_x(const float* __restrict__ x)
{
    int idx = blockIdx.x * 256 + threadIdx.x;     // b*512+n
    float4 v0 = ((const float4*)x)[2*idx];
    float4 v1 = ((const float4*)x)[2*idx + 1];
    float v[8] = {v0.x,v0.y,v0.z,v0.w,v1.x,v1.y,v1.z,v1.w};
    #pragma unroll
    for (int i = 0; i < 8; ++i) {
        __nv_bfloat16 h, l; split2(v[i], h, l);
        g_xh[(size_t)i*BN + idx] = h;
        g_xl[(size_t)i*BN + idx] = l;
    }
}

__global__ void __launch_bounds__(256) k_prep_w(const float* __restrict__ w_right,
                                                const float* __restrict__ weight,
                                                const float* __restrict__ w_left)
{
    int idx = blockIdx.x * 256 + threadIdx.x;     // m*512+n
    float4 wr4 = ((const float4*)w_right)[idx];
    float wv[4] = {wr4.x, wr4.y, wr4.z, wr4.w};
    #pragma unroll
    for (int g = 0; g < 4; ++g) {
        __nv_bfloat16 h, l; split2(wv[g], h, l);
        g_wrh[(size_t)g*MN + idx] = h;
        g_wrl[(size_t)g*MN + idx] = l;
    }
    int m = idx >> 9, n = idx & (NIN - 1);
    const float* wp  = weight + (size_t)idx * 20;
    const float* wlp = w_left + (size_t)idx * 4;
    size_t base = (size_t)m * WCOLS + n;
    #pragma unroll
    for (int c = 0; c < NC; ++c) {
        int s = cc_wsrc[c];
        float v = (s < 4) ? wlp[s] : wp[s - 4];
        __nv_bfloat16 h, l; split2(v, h, l);
        g_Wbh[base + (size_t)c * NIN] = h;
        g_Wbl[base + (size_t)c * NIN] = l;
    }
}

// ---------------------------------------------------------------------------
// GEMM body: 128x128 CTA tile, 8 warps (2x4), warp tile 64x32, K-tile 64,
// 4-stage cp.async pipeline, ldmatrix + mma.m16n8k16.bf16, fp32 accum.
// C = alpha * ( Ah·Bh + Al·Bh + Ah·Bl  [+ bias] )
// A rows = output rows, B rows = output cols, both k-contiguous (lda/ldb elems).
// ---------------------------------------------------------------------------
__device__ void gemm_body(const __nv_bfloat16* Ah, const __nv_bfloat16* Al,
                          int lda, int arow0, int acol0,
                          const __nv_bfloat16* Bh, const __nv_bfloat16* Bl,
                          int ldb, int brow0, int bcol0,
                          int K, float* Ctile, int ldc,
                          float alpha, const float* bias)
{
    extern __shared__ char smem[];
    const uint32_t sb = smem_u32(smem);
    const int tid  = threadIdx.x;
    const int wid  = tid >> 5;
    const int lane = tid & 31;
    const int wm   = wid >> 2;       // 0..1
    const int wn   = wid & 3;        // 0..3

    const int nkp = K >> 6;          // K-tiles per phase
    const int nkt = 3 * nkp;         // total tiles (3 split phases)
    const size_t ldaB = (size_t)lda * 2, ldbB = (size_t)ldb * 2;

    auto load_tile = [&](int s, int kt) {
        int phase = kt / nkp;
        int kk    = (kt - phase * nkp) << 6;
        const char* Ab = (const char*)((phase == 1) ? Al : Ah);
        const char* Bb = (const char*)((phase == 2) ? Bl : Bh);
        uint32_t sa  = sb + (uint32_t)s * STAGE_BYTES;
        uint32_t sbm = sa + MAT_BYTES;
        size_t aoff = (size_t)(acol0 + kk) * 2;
        size_t boff = (size_t)(bcol0 + kk) * 2;
        #pragma unroll
        for (int q = 0; q < 4; ++q) {
            int ch = q * 256 + tid;               // 1024 chunks of 16B
            int row = ch >> 3, c16 = ch & 7;
            cp16(sa + (uint32_t)(row * ROWSTRIDE + c16 * 16),
                 Ab + (size_t)(arow0 + row) * ldaB + aoff + c16 * 16);
        }
        #pragma unroll
        for (int q = 0; q < 4; ++q) {
            int ch = q * 256 + tid;
            int row = ch >> 3, c16 = ch & 7;
            cp16(sbm + (uint32_t)(row * ROWSTRIDE + c16 * 16),
                 Bb + (size_t)(brow0 + row) * ldbB + boff + c16 * 16);
        }
    };

    float acc[4][4][4];
    #pragma unroll
    for (int i = 0; i < 4; ++i)
        #pragma unroll
        for (int j = 0; j < 4; ++j)
            #pragma unroll
            for (int q = 0; q < 4; ++q) acc[i][j][q] = 0.f;

    // prologue: fill SSTAGES-1 stages
    #pragma unroll
    for (int s = 0; s < SSTAGES - 1; ++s) {
        load_tile(s, s);
        asm volatile("cp.async.commit_group;");
    }

    // precomputed per-lane ldmatrix address components
    const int a_row = (lane & 15);
    const int a_k8  = (lane >> 4) * 8;
    const int b_g   = lane >> 3;
    const int b_row = (b_g >> 1) * 8 + (lane & 7);
    const int b_k8  = (b_g & 1) * 8;

    for (int it = 0; it < nkt; ++it) {
        asm volatile("cp.async.wait_group %0;" :: "n"(SSTAGES - 2));
        __syncthreads();

        uint32_t sa  = sb + (uint32_t)(it % SSTAGES) * STAGE_BYTES;
        uint32_t sbm = sa + MAT_BYTES;
        #pragma unroll
        for (int k16 = 0; k16 < KT / 16; ++k16) {
            uint32_t a[4][4], b[8];
            #pragma unroll
            for (int tm = 0; tm < 4; ++tm) {
                uint32_t addr = sa
                    + (uint32_t)((wm * 64 + tm * 16 + a_row) * ROWSTRIDE)
                    + (uint32_t)((k16 * 16 + a_k8) * 2);
                ldsm4(a[tm], addr);
            }
            #pragma unroll
            for (int h = 0; h < 2; ++h) {
                uint32_t addr = sbm
                    + (uint32_t)((wn * 32 + h * 16 + b_row) * ROWSTRIDE)
                    + (uint32_t)((k16 * 16 + b_k8) * 2);
                ldsm4(&b[h * 4], addr);
            }
            #pragma unroll
            for (int tm = 0; tm < 4; ++tm)
                #pragma unroll
                for (int tn = 0; tn < 4; ++tn)
                    mma16816(acc[tm][tn], a[tm], b[2*tn], b[2*tn + 1]);
        }

        int nt = it + SSTAGES - 1;
        if (nt < nkt) load_tile(nt % SSTAGES, nt);
        asm volatile("cp.async.commit_group;");
    }

    // epilogue
    const int g = lane >> 2, t = lane & 3;
    const int row0 = wm * 64, col0 = wn * 32;
    #pragma unroll
    for (int tm = 0; tm < 4; ++tm) {
        #pragma unroll
        for (int tn = 0; tn < 4; ++tn) {
            int r = row0 + tm * 16 + g;
            int c = col0 + tn * 8 + 2 * t;
            float b0 = 0.f, b1 = 0.f;
            if (bias) { b0 = bias[c]; b1 = bias[c + 1]; }
            float2 v0 = make_float2((acc[tm][tn][0] + b0) * alpha,
                                    (acc[tm][tn][1] + b1) * alpha);
            float2 v1 = make_float2((acc[tm][tn][2] + b0) * alpha,
                                    (acc[tm][tn][3] + b1) * alpha);
            *(float2*)&Ctile[(size_t)r * ldc + c]       = v0;
            *(float2*)&Ctile[(size_t)(r + 8) * ldc + c] = v1;
        }
    }
}

__global__ void __launch_bounds__(256, 1) k_gemm1()
{
    int z = blockIdx.z;
    gemm_body(g_xh, g_xl, NIN, z*2048 + blockIdx.y*128, 0,
              g_wrh, g_wrl, NIN, cc_grade[z]*512 + blockIdx.x*128, 0,
              512,
              g_xr + (size_t)z*BN + (size_t)blockIdx.y*128*NIN + blockIdx.x*128, NIN,
              1.0f, nullptr);
}

__global__ void __launch_bounds__(256, 1) k_gemm2(const float* __restrict__ b_left)
{
    int z  = blockIdx.z;
    int st = cc_start[z] * NIN;
    gemm_body(g_Fh, g_Fl, WCOLS, blockIdx.y*128, st,
              g_Wbh, g_Wbl, WCOLS, blockIdx.x*128, st,
              cc_cnt[z] * NIN,
              g_outT + (size_t)z*BN + (size_t)blockIdx.y*128*NIN + blockIdx.x*128, NIN,
              0.7071067811865475f,
              (z == 0) ? (b_left + blockIdx.x*128) : nullptr);
}

// ---------------------------------------------------------------------------
__device__ __forceinline__ float sigf(float a) { return 1.0f / (1.0f + expf(-a)); }

__global__ void __launch_bounds__(256) k_features(const float* __restrict__ x,
                                                  const float* __restrict__ norm_a)
{
    int idx = blockIdx.x * 256 + threadIdx.x;   // b*512+n
    int n = idx & (NIN - 1);
    int b = idx >> 9;

    float4 v0 = ((const float4*)x)[2*idx];
    float4 v1 = ((const float4*)x)[2*idx + 1];
    float x0=v0.x, x1=v0.y, x2=v0.z, x3=v0.w, x4=v1.x, x5=v1.y, x6=v1.z, x7=v1.w;

    float r0=g_xr[0u*BN+idx], r1=g_xr[1u*BN+idx], r2=g_xr[2u*BN+idx],
          r3=g_xr[3u*BN+idx], r4=g_xr[4u*BN+idx], r5=g_xr[5u*BN+idx],
          r6=g_xr[6u*BN+idx], r7=g_xr[7u*BN+idx];

    float4 na = ((const float4*)norm_a)[n];
    float s0 = r0*r0;
    float s1 = r1*r1 + r2*r2 + r3*r3;
    float s2 = r4*r4 + r5*r5 + r6*r6;
    float s3 = r7*r7;
    float i0 = 1.0f / (sigf(na.x) * (sqrtf(s0) - 1.0f) + 1.0f + 1e-6f);
    float i1 = 1.0f / (sigf(na.y) * (sqrtf(s1) - 1.0f) + 1.0f + 1e-6f);
    float i2 = 1.0f / (sigf(na.z) * (sqrtf(s2) - 1.0f) + 1.0f + 1e-6f);
    float i3 = 1.0f / (sigf(na.w) * (sqrtf(s3) - 1.0f) + 1.0f + 1e-6f);
    r0*=i0; r1*=i1; r2*=i1; r3*=i1; r4*=i2; r5*=i2; r6*=i2; r7*=i3;

    float f[NC];
    f[0]=x0;  f[1]=x0*r0;
    f[2]=x1*r1 + x2*r2 + x3*r3;
    f[3]=-(x4*r4 + x5*r5 + x6*r6);
    f[4]=-x7*r7;
    f[5]=x1;  f[6]=x0*r1;  f[7]=x1*r0;
    f[8]=-x2*r4 - x3*r5;   f[9]= x4*r2 + x5*r3;
    f[10]=-x6*r7;          f[11]=-x7*r6;
    f[12]=x2; f[13]=x0*r2; f[14]=x2*r0;
    f[15]= x1*r4 - x3*r6;  f[16]=-x4*r1 + x6*r3;
    f[17]= x5*r7;          f[18]= x7*r5;
    f[19]=x3; f[20]=x0*r3; f[21]=x3*r0;
    f[22]= x1*r5 + x2*r6;  f[23]=-x5*r1 - x6*r2;
    f[24]=-x4*r7;          f[25]=-x7*r4;
    f[26]=x4; f[27]=x0*r4; f[28]= x1*r2 - x2*r1;
    f[29]= x3*r7;          f[30]= x4*r0;
    f[31]=-x5*r6 + x6*r5;  f[32]= x7*r3;
    f[33]=x5; f[34]=x0*r5; f[35]= x1*r3 - x3*r1;
    f[36]=-x2*r7;          f[37]= x5*r0;
    f[38]= x4*r6 - x6*r4;  f[39]=-x7*r2;
    f[40]=x6; f[41]=x0*r6; f[42]= x2*r3 - x3*r2;
    f[43]= x1*r7;          f[44]= x6*r0;
    f[45]=-x4*r5 + x5*r4;  f[46]= x7*r1;
    f[47]=x7; f[48]=x0*r7;
    f[49]= x1*r6 - x2*r5 + x3*r4;
    f[50]= x4*r3 - x5*r2 + x6*r1;
    f[51]= x7*r0;

    size_t base = (size_t)b * WCOLS + n;
    #pragma unroll
    for (int c = 0; c < NC; ++c) {
        __nv_bfloat16 h, l; split2(f[c], h, l);
        g_Fh[base + (size_t)c * NIN] = h;
        g_Fl[base + (size_t)c * NIN] = l;
    }
}

__global__ void __launch_bounds__(256) k_finalize(float* __restrict__ out)
{
    int idx = blockIdx.x * 256 + threadIdx.x;   // b*512+m
    float4 v0, v1;
    v0.x = g_outT[0u*BN + idx];  v0.y = g_outT[1u*BN + idx];
    v0.z = g_outT[2u*BN + idx];  v0.w = g_outT[3u*BN + idx];
    v1.x = g_outT[4u*BN + idx];  v1.y = g_outT[5u*BN + idx];
    v1.z = g_outT[6u*BN + idx];  v1.w = g_outT[7u*BN + idx];
    ((float4*)out)[2*idx]     = v0;
    ((float4*)out)[2*idx + 1] = v1;
}

// ---------------------------------------------------------------------------
extern "C" void kernel_launch(void* const* d_in, const int* in_sizes, int n_in,
                              void* d_out, int out_size)
{
    const float* x       = (const float*)d_in[0];
    const float* weight  = (const float*)d_in[1];
    const float* w_right = (const float*)d_in[2];
    const float* w_left  = (const float*)d_in[3];
    const float* b_left  = (const float*)d_in[4];
    const float* norm_a  = (const float*)d_in[5];
    float* out = (float*)d_out;

    cudaFuncSetAttribute(k_gemm1, cudaFuncAttributeMaxDynamicSharedMemorySize, SMEM_BYTES);
    cudaFuncSetAttribute(k_gemm2, cudaFuncAttributeMaxDynamicSharedMemorySize, SMEM_BYTES);

    k_split_x<<<BN / 256, 256>>>(x);
    k_prep_w <<<MN / 256, 256>>>(w_right, weight, w_left);

    dim3 gg(NOUT / 128, BB / 128, 8);
    k_gemm1<<<gg, 256, SMEM_BYTES>>>();
    k_features<<<BN / 256, 256>>>(x, norm_a);
    k_gemm2<<<gg, 256, SMEM_BYTES>>>(b_left);
    k_finalize<<<BN / 256, 256>>>(out);
}

// round 12
// speedup vs baseline: 2.2711x; 1.0302x over previous
#include <cuda_runtime.h>
#include <cuda_bf16.h>
#include <math.h>
#include <stdint.h>

// ---------------------------------------------------------------------------
// FullyConnectedSteerableGeometricProductLayer — mma.sync split-bf16 version
//
//  C_fp32 ≈ Ah·Bh + Al·Bh + Ah·Bl  (bf16 hi/lo split, fp32 accumulators)
//
//  GEMM engine: 128x256 CTA tile, 8 warps (2x4), 64x64 warp tiles,
//  K-tile 64, 3-stage cp.async pipeline, ldmatrix + mma.m16n8k16.
//  (square warp tiles: 0.064 B smem / MAC vs 0.094 before — smem-BW relief)
// ---------------------------------------------------------------------------

#define BB   2048
#define NIN  512
#define NOUT 512
#define BN   (BB*NIN)            // 1048576
#define MN   (NOUT*NIN)          // 262144
#define NC   52
#define WCOLS (NC*NIN)           // 26624

// GEMM tiling
#define CTAM 128
#define CTAN 256
#define KT   64
#define SSTAGES 3
#define ROWSTRIDE 144                       // 128B data + 16B pad (9 chunks, odd)
#define A_BYTES (CTAM*ROWSTRIDE)            // 18432
#define B_BYTES (CTAN*ROWSTRIDE)            // 36864
#define STAGE_BYTES (A_BYTES+B_BYTES)       // 55296
#define SMEM_BYTES (SSTAGES*STAGE_BYTES)    // 165888

// scratch (static device arrays; no allocation anywhere)
__device__ __align__(256) __nv_bfloat16 g_xh [8u*BN];
__device__ __align__(256) __nv_bfloat16 g_xl [8u*BN];
__device__ __align__(256) __nv_bfloat16 g_wrh[4u*MN];
__device__ __align__(256) __nv_bfloat16 g_wrl[4u*MN];
__device__ __align__(256) __nv_bfloat16 g_Wbh[(size_t)NOUT*WCOLS];
__device__ __align__(256) __nv_bfloat16 g_Wbl[(size_t)NOUT*WCOLS];
__device__ __align__(256) __nv_bfloat16 g_Fh [(size_t)BB*WCOLS];
__device__ __align__(256) __nv_bfloat16 g_Fl [(size_t)BB*WCOLS];
__device__ __align__(256) float         g_xr  [8u*BN];
__device__ __align__(256) float         g_outT[8u*BN];

__constant__ int cc_grade[8] = {0,1,1,1,2,2,2,3};
__constant__ int cc_start[8] = {0,5,12,19,26,33,40,47};
__constant__ int cc_cnt [8]  = {5,7,7,7,7,7,7,5};
__constant__ int cc_wsrc[NC] = {
    0, 4, 8,14,20,
    1, 5, 9,10,15,16,21,
    1, 5, 9,10,15,16,21,
    1, 5, 9,10,15,16,21,
    2, 6,11,12,17,18,22,
    2, 6,11,12,17,18,22,
    2, 6,11,12,17,18,22,
    3, 7,13,19,23
};

// ---------------------------------------------------------------------------
// helpers
// ---------------------------------------------------------------------------
__device__ __forceinline__ uint32_t smem_u32(const void* p) {
    uint32_t a;
    asm("{ .reg .u64 t; cvta.to.shared.u64 t, %1; cvt.u32.u64 %0, t; }"
        : "=r"(a) : "l"(p));
    return a;
}
__device__ __forceinline__ void cp16(uint32_t dst, const void* src) {
    asm volatile("cp.async.cg.shared.global [%0], [%1], 16;"
                 :: "r"(dst), "l"(__cvta_generic_to_global(src)));
}
__device__ __forceinline__ void ldsm4(uint32_t* r, uint32_t addr) {
    asm volatile("ldmatrix.sync.aligned.m8n8.x4.shared.b16 {%0,%1,%2,%3}, [%4];"
        : "=r"(r[0]), "=r"(r[1]), "=r"(r[2]), "=r"(r[3]) : "r"(addr));
}
__device__ __forceinline__ void mma16816(float* c, const uint32_t* a,
                                         uint32_t b0, uint32_t b1) {
    asm volatile("mma.sync.aligned.m16n8k16.row.col.f32.bf16.bf16.f32 "
        "{%0,%1,%2,%3}, {%4,%5,%6,%7}, {%8,%9}, {%0,%1,%2,%3};"
        : "+f"(c[0]), "+f"(c[1]), "+f"(c[2]), "+f"(c[3])
        : "r"(a[0]), "r"(a[1]), "r"(a[2]), "r"(a[3]), "r"(b0), "r"(b1));
}
__device__ __forceinline__ void split2(float v, __nv_bfloat16& h, __nv_bfloat16& l) {
    h = __float2bfloat16(v);
    l = __float2bfloat16(v - __bfloat162float(h));
}

// ---------------------------------------------------------------------------
// prep kernels
// ---------------------------------------------------------------------------
__global__ void __launch_bounds__(256) k_split_x(const float* __restrict__ x)
{
    int idx = blockIdx.x * 256 + threadIdx.x;     // b*512+n
    float4 v0 = ((const float4*)x)[2*idx];
    float4 v1 = ((const float4*)x)[2*idx + 1];
    float v[8] = {v0.x,v0.y,v0.z,v0.w,v1.x,v1.y,v1.z,v1.w};
    #pragma unroll
    for (int i = 0; i < 8; ++i) {
        __nv_bfloat16 h, l; split2(v[i], h, l);
        g_xh[(size_t)i*BN + idx] = h;
        g_xl[(size_t)i*BN + idx] = l;
    }
}

__global__ void __launch_bounds__(256) k_prep_w(const float* __restrict__ w_right,
                                                const float* __restrict__ weight,
                                                const float* __restrict__ w_left)
{
    int idx = blockIdx.x * 256 + threadIdx.x;     // m*512+n
    float4 wr4 = ((const float4*)w_right)[idx];
    float wv[4] = {wr4.x, wr4.y, wr4.z, wr4.w};
    #pragma unroll
    for (int g = 0; g < 4; ++g) {
        __nv_bfloat16 h, l; split2(wv[g], h, l);
        g_wrh[(size_t)g*MN + idx] = h;
        g_wrl[(size_t)g*MN + idx] = l;
    }
    int m = idx >> 9, n = idx & (NIN - 1);
    const float* wp  = weight + (size_t)idx * 20;
    const float* wlp = w_left + (size_t)idx * 4;
    size_t base = (size_t)m * WCOLS + n;
    #pragma unroll
    for (int c = 0; c < NC; ++c) {
        int s = cc_wsrc[c];
        float v = (s < 4) ? wlp[s] : wp[s - 4];
        __nv_bfloat16 h, l; split2(v, h, l);
        g_Wbh[base + (size_t)c * NIN] = h;
        g_Wbl[base + (size_t)c * NIN] = l;
    }
}

// ---------------------------------------------------------------------------
// GEMM body: 128x256 CTA tile, 8 warps (2x4), warp tile 64x64, K-tile 64,
// 3-stage cp.async pipeline, ldmatrix + mma.m16n8k16.bf16, fp32 accum.
// C = alpha * ( Ah·Bh + Al·Bh + Ah·Bl  [+ bias] )
// A rows = output rows, B rows = output cols, both k-contiguous.
// ---------------------------------------------------------------------------
__device__ void gemm_body(const __nv_bfloat16* Ah, const __nv_bfloat16* Al,
                          int lda, int arow0, int acol0,
                          const __nv_bfloat16* Bh, const __nv_bfloat16* Bl,
                          int ldb, int brow0, int bcol0,
                          int K, float* Ctile, int ldc,
                          float alpha, const float* bias)
{
    extern __shared__ char smem[];
    const uint32_t sb = smem_u32(smem);
    const int tid  = threadIdx.x;
    const int wid  = tid >> 5;
    const int lane = tid & 31;
    const int wm   = wid >> 2;       // 0..1  (64-row block)
    const int wn   = wid & 3;        // 0..3  (64-col block)

    const int nkp = K >> 6;          // K-tiles per phase
    const int nkt = 3 * nkp;         // total tiles (3 split phases)
    const size_t ldaB = (size_t)lda * 2, ldbB = (size_t)ldb * 2;

    auto load_tile = [&](int s, int kt) {
        int phase = kt / nkp;
        int kk    = (kt - phase * nkp) << 6;
        const char* Ab = (const char*)((phase == 1) ? Al : Ah);
        const char* Bb = (const char*)((phase == 2) ? Bl : Bh);
        uint32_t sa  = sb + (uint32_t)s * STAGE_BYTES;
        uint32_t sbm = sa + A_BYTES;
        size_t aoff = (size_t)(acol0 + kk) * 2;
        size_t boff = (size_t)(bcol0 + kk) * 2;
        #pragma unroll
        for (int q = 0; q < 4; ++q) {          // A: 1024 chunks of 16B
            int ch = q * 256 + tid;
            int row = ch >> 3, c16 = ch & 7;
            cp16(sa + (uint32_t)(row * ROWSTRIDE + c16 * 16),
                 Ab + (size_t)(arow0 + row) * ldaB + aoff + c16 * 16);
        }
        #pragma unroll
        for (int q = 0; q < 8; ++q) {          // B: 2048 chunks of 16B
            int ch = q * 256 + tid;
            int row = ch >> 3, c16 = ch & 7;
            cp16(sbm + (uint32_t)(row * ROWSTRIDE + c16 * 16),
                 Bb + (size_t)(brow0 + row) * ldbB + boff + c16 * 16);
        }
    };

    float acc[4][8][4];
    #pragma unroll
    for (int i = 0; i < 4; ++i)
        #pragma unroll
        for (int j = 0; j < 8; ++j)
            #pragma unroll
            for (int q = 0; q < 4; ++q) acc[i][j][q] = 0.f;

    // prologue: fill SSTAGES-1 stages
    #pragma unroll
    for (int s = 0; s < SSTAGES - 1; ++s) {
        load_tile(s, s);
        asm volatile("cp.async.commit_group;");
    }

    // per-lane ldmatrix address components
    const int a_row = (lane & 15);
    const int a_k8  = (lane >> 4) * 8;
    const int b_g   = lane >> 3;
    const int b_row = (b_g >> 1) * 8 + (lane & 7);
    const int b_k8  = (b_g & 1) * 8;

    for (int it = 0; it < nkt; ++it) {
        asm volatile("cp.async.wait_group %0;" :: "n"(SSTAGES - 2));
        __syncthreads();

        uint32_t sa  = sb + (uint32_t)(it % SSTAGES) * STAGE_BYTES;
        uint32_t sbm = sa + A_BYTES;
        #pragma unroll
        for (int k16 = 0; k16 < KT / 16; ++k16) {
            uint32_t a[4][4], b[16];
            #pragma unroll
            for (int tm = 0; tm < 4; ++tm) {
                uint32_t addr = sa
                    + (uint32_t)((wm * 64 + tm * 16 + a_row) * ROWSTRIDE)
                    + (uint32_t)((k16 * 16 + a_k8) * 2);
                ldsm4(a[tm], addr);
            }
            #pragma unroll
            for (int h = 0; h < 4; ++h) {
                uint32_t addr = sbm
                    + (uint32_t)((wn * 64 + h * 16 + b_row) * ROWSTRIDE)
                    + (uint32_t)((k16 * 16 + b_k8) * 2);
                ldsm4(&b[h * 4], addr);
            }
            #pragma unroll
            for (int tm = 0; tm < 4; ++tm)
                #pragma unroll
                for (int tn = 0; tn < 8; ++tn)
                    mma16816(acc[tm][tn], a[tm], b[2*tn], b[2*tn + 1]);
        }

        int nt = it + SSTAGES - 1;
        if (nt < nkt) load_tile(nt % SSTAGES, nt);
        asm volatile("cp.async.commit_group;");
    }

    // epilogue
    const int g = lane >> 2, t = lane & 3;
    const int row0 = wm * 64, col0 = wn * 64;
    #pragma unroll
    for (int tm = 0; tm < 4; ++tm) {
        #pragma unroll
        for (int tn = 0; tn < 8; ++tn) {
            int r = row0 + tm * 16 + g;
            int c = col0 + tn * 8 + 2 * t;
            float b0 = 0.f, b1 = 0.f;
            if (bias) { b0 = bias[c]; b1 = bias[c + 1]; }
            float2 v0 = make_float2((acc[tm][tn][0] + b0) * alpha,
                                    (acc[tm][tn][1] + b1) * alpha);
            float2 v1 = make_float2((acc[tm][tn][2] + b0) * alpha,
                                    (acc[tm][tn][3] + b1) * alpha);
            *(float2*)&Ctile[(size_t)r * ldc + c]       = v0;
            *(float2*)&Ctile[(size_t)(r + 8) * ldc + c] = v1;
        }
    }
}

__global__ void __launch_bounds__(256, 1) k_gemm1()
{
    int z = blockIdx.z;
    gemm_body(g_xh, g_xl, NIN, z*2048 + blockIdx.y*CTAM, 0,
              g_wrh, g_wrl, NIN, cc_grade[z]*512 + blockIdx.x*CTAN, 0,
              512,
              g_xr + (size_t)z*BN + (size_t)blockIdx.y*CTAM*NIN + blockIdx.x*CTAN, NIN,
              1.0f, nullptr);
}

__global__ void __launch_bounds__(256, 1) k_gemm2(const float* __restrict__ b_left)
{
    int z  = blockIdx.z;
    int st = cc_start[z] * NIN;
    gemm_body(g_Fh, g_Fl, WCOLS, blockIdx.y*CTAM, st,
              g_Wbh, g_Wbl, WCOLS, blockIdx.x*CTAN, st,
              cc_cnt[z] * NIN,
              g_outT + (size_t)z*BN + (size_t)blockIdx.y*CTAM*NIN + blockIdx.x*CTAN, NIN,
              0.7071067811865475f,
              (z == 0) ? (b_left + blockIdx.x*CTAN) : nullptr);
}

// ---------------------------------------------------------------------------
__device__ __forceinline__ float sigf(float a) { return 1.0f / (1.0f + expf(-a)); }

__global__ void __launch_bounds__(256) k_features(const float* __restrict__ x,
                                                  const float* __restrict__ norm_a)
{
    int idx = blockIdx.x * 256 + threadIdx.x;   // b*512+n
    int n = idx & (NIN - 1);
    int b = idx >> 9;

    float4 v0 = ((const float4*)x)[2*idx];
    float4 v1 = ((const float4*)x)[2*idx + 1];
    float x0=v0.x, x1=v0.y, x2=v0.z, x3=v0.w, x4=v1.x, x5=v1.y, x6=v1.z, x7=v1.w;

    float r0=g_xr[0u*BN+idx], r1=g_xr[1u*BN+idx], r2=g_xr[2u*BN+idx],
          r3=g_xr[3u*BN+idx], r4=g_xr[4u*BN+idx], r5=g_xr[5u*BN+idx],
          r6=g_xr[6u*BN+idx], r7=g_xr[7u*BN+idx];

    float4 na = ((const float4*)norm_a)[n];
    float s0 = r0*r0;
    float s1 = r1*r1 + r2*r2 + r3*r3;
    float s2 = r4*r4 + r5*r5 + r6*r6;
    float s3 = r7*r7;
    float i0 = 1.0f / (sigf(na.x) * (sqrtf(s0) - 1.0f) + 1.0f + 1e-6f);
    float i1 = 1.0f / (sigf(na.y) * (sqrtf(s1) - 1.0f) + 1.0f + 1e-6f);
    float i2 = 1.0f / (sigf(na.z) * (sqrtf(s2) - 1.0f) + 1.0f + 1e-6f);
    float i3 = 1.0f / (sigf(na.w) * (sqrtf(s3) - 1.0f) + 1.0f + 1e-6f);
    r0*=i0; r1*=i1; r2*=i1; r3*=i1; r4*=i2; r5*=i2; r6*=i2; r7*=i3;

    float f[NC];
    f[0]=x0;  f[1]=x0*r0;
    f[2]=x1*r1 + x2*r2 + x3*r3;
    f[3]=-(x4*r4 + x5*r5 + x6*r6);
    f[4]=-x7*r7;
    f[5]=x1;  f[6]=x0*r1;  f[7]=x1*r0;
    f[8]=-x2*r4 - x3*r5;   f[9]= x4*r2 + x5*r3;
    f[10]=-x6*r7;          f[11]=-x7*r6;
    f[12]=x2; f[13]=x0*r2; f[14]=x2*r0;
    f[15]= x1*r4 - x3*r6;  f[16]=-x4*r1 + x6*r3;
    f[17]= x5*r7;          f[18]= x7*r5;
    f[19]=x3; f[20]=x0*r3; f[21]=x3*r0;
    f[22]= x1*r5 + x2*r6;  f[23]=-x5*r1 - x6*r2;
    f[24]=-x4*r7;          f[25]=-x7*r4;
    f[26]=x4; f[27]=x0*r4; f[28]= x1*r2 - x2*r1;
    f[29]= x3*r7;          f[30]= x4*r0;
    f[31]=-x5*r6 + x6*r5;  f[32]= x7*r3;
    f[33]=x5; f[34]=x0*r5; f[35]= x1*r3 - x3*r1;
    f[36]=-x2*r7;          f[37]= x5*r0;
    f[38]= x4*r6 - x6*r4;  f[39]=-x7*r2;
    f[40]=x6; f[41]=x0*r6; f[42]= x2*r3 - x3*r2;
    f[43]= x1*r7;          f[44]= x6*r0;
    f[45]=-x4*r5 + x5*r4;  f[46]= x7*r1;
    f[47]=x7; f[48]=x0*r7;
    f[49]= x1*r6 - x2*r5 + x3*r4;
    f[50]= x4*r3 - x5*r2 + x6*r1;
    f[51]= x7*r0;

    size_t base = (size_t)b * WCOLS + n;
    #pragma unroll
    for (int c = 0; c < NC; ++c) {
        __nv_bfloat16 h, l; split2(f[c], h, l);
        g_Fh[base + (size_t)c * NIN] = h;
        g_Fl[base + (size_t)c * NIN] = l;
    }
}

__global__ void __launch_bounds__(256) k_finalize(float* __restrict__ out)
{
    int idx = blockIdx.x * 256 + threadIdx.x;   // b*512+m
    float4 v0, v1;
    v0.x = g_outT[0u*BN + idx];  v0.y = g_outT[1u*BN + idx];
    v0.z = g_outT[2u*BN + idx];  v0.w = g_outT[3u*BN + idx];
    v1.x = g_outT[4u*BN + idx];  v1.y = g_outT[5u*BN + idx];
    v1.z = g_outT[6u*BN + idx];  v1.w = g_outT[7u*BN + idx];
    ((float4*)out)[2*idx]     = v0;
    ((float4*)out)[2*idx + 1] = v1;
}

// ---------------------------------------------------------------------------
extern "C" void kernel_launch(void* const* d_in, const int* in_sizes, int n_in,
                              void* d_out, int out_size)
{
    const float* x       = (const float*)d_in[0];
    const float* weight  = (const float*)d_in[1];
    const float* w_right = (const float*)d_in[2];
    const float* w_left  = (const float*)d_in[3];
    const float* b_left  = (const float*)d_in[4];
    const float* norm_a  = (const float*)d_in[5];
    float* out = (float*)d_out;

    cudaFuncSetAttribute(k_gemm1, cudaFuncAttributeMaxDynamicSharedMemorySize, SMEM_BYTES);
    cudaFuncSetAttribute(k_gemm2, cudaFuncAttributeMaxDynamicSharedMemorySize, SMEM_BYTES);

    k_split_x<<<BN / 256, 256>>>(x);
    k_prep_w <<<MN / 256, 256>>>(w_right, weight, w_left);

    dim3 gg(NOUT / CTAN, BB / CTAM, 8);
    k_gemm1<<<gg, 256, SMEM_BYTES>>>();
    k_features<<<BN / 256, 256>>>(x, norm_a);
    k_gemm2<<<gg, 256, SMEM_BYTES>>>(b_left);
    k_finalize<<<BN / 256, 256>>>(out);
}